// round 2
// baseline (speedup 1.0000x reference)
#include <cuda_runtime.h>
#include <math.h>

// Problem constants (fixed by the reference)
#define S_LEN 4096
#define D_MODEL 512
#define SLOPE 0.5f
// Sliding window: keys with i-j > 96 are suppressed by >= e^{-48+~5} ~ 1e-19,
// far below the 1e-3 rel-err threshold. Band of 128 keys per 32-query tile.
#define QT 32       // query tile
#define NKEY 128    // band width (keys jstart..jstart+127, jstart = i0-96)
#define WBACK 96

// Scratch for Q = x @ W_qk and V = x @ W_v^T + b_v  (B*S x D fp32)
__device__ float g_Q[4 * S_LEN * D_MODEL];
__device__ float g_V[4 * S_LEN * D_MODEL];

// ---------------------------------------------------------------------------
// Projection GEMM: C[M,N] = A[M,K] * B' (+ bias), B' = B (transB=0, lda=N)
// or B'[k][n] = B[n][k] (transB=1). 128x128 tile, K-chunk 8, 8x8 microtile.
// ---------------------------------------------------------------------------
__global__ __launch_bounds__(256)
void gemm_proj(const float* __restrict__ A, const float* __restrict__ B,
               const float* __restrict__ bias, float* __restrict__ C,
               int M, int N, int K, int transB)
{
    __shared__ float As[8][128];
    __shared__ float Bs[8][128];

    const int tid = threadIdx.x;
    const int tx = tid & 15;        // 0..15 -> 8 cols each
    const int ty = tid >> 4;        // 0..15 -> 8 rows each
    const int m0 = blockIdx.x * 128;
    const int n0 = blockIdx.y * 128;

    float acc[8][8];
#pragma unroll
    for (int i = 0; i < 8; i++)
#pragma unroll
        for (int j = 0; j < 8; j++) acc[i][j] = 0.f;

    for (int k0 = 0; k0 < K; k0 += 8) {
        // A tile: rows m0..m0+127, k0..k0+7 -> As[k][row]
        {
            int row = tid >> 1;
            int c4  = (tid & 1) * 4;
            float4 a = *reinterpret_cast<const float4*>(
                &A[(size_t)(m0 + row) * K + k0 + c4]);
            As[c4 + 0][row] = a.x; As[c4 + 1][row] = a.y;
            As[c4 + 2][row] = a.z; As[c4 + 3][row] = a.w;
        }
        // B tile -> Bs[k][n]
        if (!transB) {
            int k = tid >> 5;
            int c = (tid & 31) * 4;
            float4 b = *reinterpret_cast<const float4*>(
                &B[(size_t)(k0 + k) * N + n0 + c]);
            *reinterpret_cast<float4*>(&Bs[k][c]) = b;
        } else {
            int e  = tid >> 1;
            int k4 = (tid & 1) * 4;
            float4 b = *reinterpret_cast<const float4*>(
                &B[(size_t)(n0 + e) * K + k0 + k4]);
            Bs[k4 + 0][e] = b.x; Bs[k4 + 1][e] = b.y;
            Bs[k4 + 2][e] = b.z; Bs[k4 + 3][e] = b.w;
        }
        __syncthreads();

#pragma unroll
        for (int kk = 0; kk < 8; kk++) {
            float a[8], b[8];
            *reinterpret_cast<float4*>(&a[0]) =
                *reinterpret_cast<float4*>(&As[kk][ty * 8]);
            *reinterpret_cast<float4*>(&a[4]) =
                *reinterpret_cast<float4*>(&As[kk][ty * 8 + 4]);
            *reinterpret_cast<float4*>(&b[0]) =
                *reinterpret_cast<float4*>(&Bs[kk][tx * 8]);
            *reinterpret_cast<float4*>(&b[4]) =
                *reinterpret_cast<float4*>(&Bs[kk][tx * 8 + 4]);
#pragma unroll
            for (int i = 0; i < 8; i++)
#pragma unroll
                for (int j = 0; j < 8; j++)
                    acc[i][j] = fmaf(a[i], b[j], acc[i][j]);
        }
        __syncthreads();
    }

    float bv[8];
#pragma unroll
    for (int j = 0; j < 8; j++)
        bv[j] = bias ? bias[n0 + tx * 8 + j] : 0.f;

#pragma unroll
    for (int i = 0; i < 8; i++) {
        int row = m0 + ty * 8 + i;
        float4 o0, o1;
        o0.x = acc[i][0] + bv[0]; o0.y = acc[i][1] + bv[1];
        o0.z = acc[i][2] + bv[2]; o0.w = acc[i][3] + bv[3];
        o1.x = acc[i][4] + bv[4]; o1.y = acc[i][5] + bv[5];
        o1.z = acc[i][6] + bv[6]; o1.w = acc[i][7] + bv[7];
        *reinterpret_cast<float4*>(&C[(size_t)row * N + n0 + tx * 8])     = o0;
        *reinterpret_cast<float4*>(&C[(size_t)row * N + n0 + tx * 8 + 4]) = o1;
    }
}

// ---------------------------------------------------------------------------
// Windowed attention: per CTA = 32 queries, 128-key band.
// Phase 1: S = Q_tile @ K_band^T  (K = x rows), scale + ALiBi + causal mask
// Phase 2: row softmax in smem
// Phase 3: out = P @ V_band
// ---------------------------------------------------------------------------
struct P1Tiles { float Qs[QT][33]; float Ks[NKEY][33]; };

__global__ __launch_bounds__(256)
void attn_win(const float* __restrict__ X, const float* __restrict__ Q,
              const float* __restrict__ V, float* __restrict__ O)
{
    __shared__ float Ssm[QT][NKEY];
    __shared__ union SU { P1Tiles p1; float Vs[8][D_MODEL]; } u;

    const int tid = threadIdx.x;
    const int tx = tid & 31;    // 0..31
    const int ty = tid >> 5;    // 0..7
    const int b  = blockIdx.y;
    const int i0 = blockIdx.x * QT;
    const int jstart = i0 - WBACK;

    const float* Xb = X + (size_t)b * S_LEN * D_MODEL;
    const float* Qb = Q + (size_t)b * S_LEN * D_MODEL;
    const float* Vb = V + (size_t)b * S_LEN * D_MODEL;

    // ---- Phase 1: band scores ----
    float acc[4][4];
#pragma unroll
    for (int i = 0; i < 4; i++)
#pragma unroll
        for (int j = 0; j < 4; j++) acc[i][j] = 0.f;

    for (int k0 = 0; k0 < D_MODEL; k0 += 32) {
        {   // Q tile 32x32
            int row = tid >> 3;
            int c4  = (tid & 7) * 4;
            float4 q = *reinterpret_cast<const float4*>(
                &Qb[(size_t)(i0 + row) * D_MODEL + k0 + c4]);
            u.p1.Qs[row][c4 + 0] = q.x; u.p1.Qs[row][c4 + 1] = q.y;
            u.p1.Qs[row][c4 + 2] = q.z; u.p1.Qs[row][c4 + 3] = q.w;
        }
#pragma unroll
        for (int r = 0; r < 4; r++) {   // K tile 128x32
            int idx  = tid + 256 * r;
            int krow = idx >> 3;
            int c4   = (idx & 7) * 4;
            int j    = jstart + krow;
            float4 kv = make_float4(0.f, 0.f, 0.f, 0.f);
            if (j >= 0)
                kv = *reinterpret_cast<const float4*>(
                    &Xb[(size_t)j * D_MODEL + k0 + c4]);
            u.p1.Ks[krow][c4 + 0] = kv.x; u.p1.Ks[krow][c4 + 1] = kv.y;
            u.p1.Ks[krow][c4 + 2] = kv.z; u.p1.Ks[krow][c4 + 3] = kv.w;
        }
        __syncthreads();

#pragma unroll
        for (int kk = 0; kk < 32; kk++) {
            float q[4], kv[4];
#pragma unroll
            for (int ri = 0; ri < 4; ri++) q[ri]  = u.p1.Qs[ty + 8 * ri][kk];
#pragma unroll
            for (int ci = 0; ci < 4; ci++) kv[ci] = u.p1.Ks[tx + 32 * ci][kk];
#pragma unroll
            for (int ri = 0; ri < 4; ri++)
#pragma unroll
                for (int ci = 0; ci < 4; ci++)
                    acc[ri][ci] = fmaf(q[ri], kv[ci], acc[ri][ci]);
        }
        __syncthreads();
    }

    const float scale = 0.04419417382415922f;  // 1/sqrt(512)
#pragma unroll
    for (int ri = 0; ri < 4; ri++) {
        int i = i0 + ty + 8 * ri;
#pragma unroll
        for (int ci = 0; ci < 4; ci++) {
            int c = tx + 32 * ci;
            int j = jstart + c;
            float s;
            if (j < 0 || j > i) s = -1e30f;
            else s = acc[ri][ci] * scale + SLOPE * (float)(j - i);
            Ssm[ty + 8 * ri][c] = s;
        }
    }
    __syncthreads();

    // ---- Phase 2: softmax (8 threads per row) ----
    {
        int r = tid >> 3;
        int l = tid & 7;
        float m = -1e30f;
        for (int c = l * 16; c < l * 16 + 16; c++) m = fmaxf(m, Ssm[r][c]);
#pragma unroll
        for (int o = 4; o > 0; o >>= 1)
            m = fmaxf(m, __shfl_xor_sync(0xffffffffu, m, o));
        float sum = 0.f;
        for (int c = l * 16; c < l * 16 + 16; c++) {
            float e = __expf(Ssm[r][c] - m);
            Ssm[r][c] = e;
            sum += e;
        }
#pragma unroll
        for (int o = 4; o > 0; o >>= 1)
            sum += __shfl_xor_sync(0xffffffffu, sum, o);
        float inv = 1.f / sum;
        for (int c = l * 16; c < l * 16 + 16; c++) Ssm[r][c] *= inv;
    }
    __syncthreads();

    // ---- Phase 3: out = P @ V_band ----
    float out[4][16];
#pragma unroll
    for (int ri = 0; ri < 4; ri++)
#pragma unroll
        for (int ci = 0; ci < 16; ci++) out[ri][ci] = 0.f;

    for (int kc = 0; kc < NKEY; kc += 8) {
#pragma unroll
        for (int r = 0; r < 4; r++) {   // V chunk 8x512
            int idx  = tid + 256 * r;           // float4 index 0..1023
            int vrow = idx >> 7;                // 0..7
            int c4   = (idx & 127) * 4;
            int j    = jstart + kc + vrow;
            float4 vv = make_float4(0.f, 0.f, 0.f, 0.f);
            if (j >= 0)
                vv = *reinterpret_cast<const float4*>(
                    &Vb[(size_t)j * D_MODEL + c4]);
            *reinterpret_cast<float4*>(&u.Vs[vrow][c4]) = vv;
        }
        __syncthreads();

#pragma unroll
        for (int k = 0; k < 8; k++) {
            float p[4];
#pragma unroll
            for (int ri = 0; ri < 4; ri++) p[ri] = Ssm[ty + 8 * ri][kc + k];
#pragma unroll
            for (int ci = 0; ci < 16; ci++) {
                float v = u.Vs[k][tx + 32 * ci];
#pragma unroll
                for (int ri = 0; ri < 4; ri++)
                    out[ri][ci] = fmaf(p[ri], v, out[ri][ci]);
            }
        }
        __syncthreads();
    }

#pragma unroll
    for (int ri = 0; ri < 4; ri++) {
        int row = i0 + ty + 8 * ri;
#pragma unroll
        for (int ci = 0; ci < 16; ci++)
            O[((size_t)b * S_LEN + row) * D_MODEL + tx + 32 * ci] = out[ri][ci];
    }
}

// ---------------------------------------------------------------------------
extern "C" void kernel_launch(void* const* d_in, const int* in_sizes, int n_in,
                              void* d_out, int out_size)
{
    const float* x   = (const float*)d_in[0];
    const float* Wqk = (const float*)d_in[1];
    const float* Wv  = (const float*)d_in[2];
    const float* bv  = (const float*)d_in[3];
    float* out = (float*)d_out;

    const int B = in_sizes[0] / (S_LEN * D_MODEL);  // 4
    const int M = B * S_LEN;                        // 16384

    float *Qp = nullptr, *Vp = nullptr;
    cudaGetSymbolAddress((void**)&Qp, g_Q);
    cudaGetSymbolAddress((void**)&Vp, g_V);

    dim3 gproj(M / 128, D_MODEL / 128);
    gemm_proj<<<gproj, 256>>>(x, Wqk, nullptr, Qp, M, D_MODEL, D_MODEL, 0);
    gemm_proj<<<gproj, 256>>>(x, Wv,  bv,      Vp, M, D_MODEL, D_MODEL, 1);

    dim3 gattn(S_LEN / QT, B);
    attn_win<<<gattn, 256>>>(x, Qp, Vp, out);
}

// round 4
// speedup vs baseline: 1.1962x; 1.1962x over previous
#include <cuda_runtime.h>
#include <cuda_bf16.h>
#include <cstdint>
#include <math.h>

// Problem constants
#define S_LEN 4096
#define D_MODEL 512
#define SLOPE 0.5f
#define QT 32
#define NKEY 128
#define WBACK 96
#define NB 4

// Scratch
__device__ float g_Q[NB * S_LEN * D_MODEL];
__device__ float g_V[NB * S_LEN * D_MODEL];
// Packed weights [Wqk | Wv^T] as bf16 hi/lo planes, layout [n][k] (K-major rows)
__device__ __nv_bfloat16 g_Whi[1024 * 512];
__device__ __nv_bfloat16 g_Wlo[1024 * 512];

// ---------------------------------------------------------------------------
// mma.sync helper: D += A(16x16 bf16) * B(16x8 bf16), fp32 accum
// ---------------------------------------------------------------------------
__device__ __forceinline__ void mma16816(float* d, const uint32_t* a,
                                         uint32_t b0, uint32_t b1)
{
    asm volatile(
        "mma.sync.aligned.m16n8k16.row.col.f32.bf16.bf16.f32 "
        "{%0,%1,%2,%3}, {%4,%5,%6,%7}, {%8,%9}, {%0,%1,%2,%3};"
        : "+f"(d[0]), "+f"(d[1]), "+f"(d[2]), "+f"(d[3])
        : "r"(a[0]), "r"(a[1]), "r"(a[2]), "r"(a[3]), "r"(b0), "r"(b1));
}

__device__ __forceinline__ uint32_t pack_bf2(float x, float y) {
    __nv_bfloat162 t = __floats2bfloat162_rn(x, y);
    return *reinterpret_cast<uint32_t*>(&t);
}

// ---------------------------------------------------------------------------
// Pack [Wqk | Wv^T] into bf16 hi/lo planes, layout [n][k]
// ---------------------------------------------------------------------------
__global__ void pack_w(const float* __restrict__ Wqk, const float* __restrict__ Wv)
{
    int idx = blockIdx.x * 256 + threadIdx.x;   // 0..524287
    int n = idx >> 9, k = idx & 511;
    float w = (n < 512) ? Wqk[k * 512 + n] : Wv[(n - 512) * 512 + k];
    __nv_bfloat16 hi = __float2bfloat16_rn(w);
    float lo = w - __bfloat162float(hi);
    g_Whi[idx] = hi;
    g_Wlo[idx] = __float2bfloat16_rn(lo);
}

// ---------------------------------------------------------------------------
// mma.sync GEMM: [Q|V][16384, 1024] = x[16384,512] @ W^T, bf16 hi/lo 3-MMA.
// CTA 128x128, 8 warps (4 m x 2 n), warp tile 32x64, K-chunk 32.
// smem planes padded to stride 40 bf16 (80 B): fragment loads conflict-free.
// ---------------------------------------------------------------------------
#define KC 32
#define STRD 40                       // bf16 stride per row
#define PLANE (128 * STRD * 2)        // 10240 bytes per plane
#define OFF_AHI 0
#define OFF_ALO PLANE
#define OFF_BHI (2 * PLANE)
#define OFF_BLO (3 * PLANE)

__global__ __launch_bounds__(256)
void mma_gemm(const float* __restrict__ X, const float* __restrict__ bias,
              float* __restrict__ Q, float* __restrict__ V)
{
    __shared__ __align__(16) char sm[4 * PLANE];   // 40 KB

    const int tid = threadIdx.x;
    const int wid = tid >> 5;
    const int lane = tid & 31;
    const int g = lane >> 2;          // 0..7
    const int t4 = lane & 3;          // 0..3
    const int warp_m = wid & 3;       // 0..3 -> rows 32*warp_m
    const int warp_n = wid >> 2;      // 0..1 -> cols 64*warp_n
    const int m0 = blockIdx.x * 128;
    const int n0 = blockIdx.y * 128;

    float acc[2][8][4];
#pragma unroll
    for (int mt = 0; mt < 2; mt++)
#pragma unroll
        for (int nt = 0; nt < 8; nt++)
#pragma unroll
            for (int i = 0; i < 4; i++) acc[mt][nt][i] = 0.f;

    for (int c = 0; c < 512 / KC; c++) {
        const int k0 = c * KC;

        // ---- global loads to regs (overlaps previous compute) ----
        float4 av[2];
#pragma unroll
        for (int i = 0; i < 2; i++) {
            int f = tid + 256 * i;            // 512 of 1024 float4s... (2 per thr x2)
            int row = f >> 3, c4 = f & 7;
            av[i] = *reinterpret_cast<const float4*>(
                &X[(size_t)(m0 + row) * 512 + k0 + c4 * 4]);
        }
        float4 av2[2];
#pragma unroll
        for (int i = 0; i < 2; i++) {
            int f = tid + 256 * (i + 2);
            int row = f >> 3, c4 = f & 7;
            av2[i] = *reinterpret_cast<const float4*>(
                &X[(size_t)(m0 + row) * 512 + k0 + c4 * 4]);
        }
        uint4 bh[2], bl[2];
#pragma unroll
        for (int i = 0; i < 2; i++) {
            int f = tid + 256 * i;            // 512 uint4 per plane
            int row = f >> 2, c8 = f & 3;
            size_t gidx = (size_t)(n0 + row) * 512 + k0 + c8 * 8;
            bh[i] = *reinterpret_cast<const uint4*>(&g_Whi[gidx]);
            bl[i] = *reinterpret_cast<const uint4*>(&g_Wlo[gidx]);
        }

        if (c) __syncthreads();   // previous compute done before overwrite

        // ---- convert + store to smem ----
#pragma unroll
        for (int i = 0; i < 4; i++) {
            float4 a = (i < 2) ? av[i] : av2[i - 2];
            int f = tid + 256 * i;
            int row = f >> 3, c4 = f & 7;
            __nv_bfloat16 h0 = __float2bfloat16_rn(a.x);
            __nv_bfloat16 h1 = __float2bfloat16_rn(a.y);
            __nv_bfloat16 h2 = __float2bfloat16_rn(a.z);
            __nv_bfloat16 h3 = __float2bfloat16_rn(a.w);
            uint32_t hx = pack_bf2(__bfloat162float(h0), __bfloat162float(h1));
            // pack hi directly from the rounded values
            __nv_bfloat162 hp0; hp0.x = h0; hp0.y = h1;
            __nv_bfloat162 hp1; hp1.x = h2; hp1.y = h3;
            uint32_t lo0 = pack_bf2(a.x - __bfloat162float(h0),
                                    a.y - __bfloat162float(h1));
            uint32_t lo1 = pack_bf2(a.z - __bfloat162float(h2),
                                    a.w - __bfloat162float(h3));
            (void)hx;
            int off = row * (STRD * 2) + c4 * 8;
            *reinterpret_cast<uint2*>(sm + OFF_AHI + off) =
                make_uint2(*(uint32_t*)&hp0, *(uint32_t*)&hp1);
            *reinterpret_cast<uint2*>(sm + OFF_ALO + off) = make_uint2(lo0, lo1);
        }
#pragma unroll
        for (int i = 0; i < 2; i++) {
            int f = tid + 256 * i;
            int row = f >> 2, c8 = f & 3;
            int off = row * (STRD * 2) + c8 * 16;
            *reinterpret_cast<uint4*>(sm + OFF_BHI + off) = bh[i];
            *reinterpret_cast<uint4*>(sm + OFF_BLO + off) = bl[i];
        }
        __syncthreads();

        // ---- compute: 2 k-steps of 16 ----
#pragma unroll
        for (int ks = 0; ks < 2; ks++) {
            const int kb = ks * 32 + t4 * 4;   // byte offset within row
            uint32_t ahi[2][4], alo[2][4];
#pragma unroll
            for (int mt = 0; mt < 2; mt++) {
                int r0 = (warp_m * 32 + mt * 16 + g) * (STRD * 2) + kb;
                int r1 = r0 + 8 * (STRD * 2);
                ahi[mt][0] = *(const uint32_t*)(sm + OFF_AHI + r0);
                ahi[mt][1] = *(const uint32_t*)(sm + OFF_AHI + r1);
                ahi[mt][2] = *(const uint32_t*)(sm + OFF_AHI + r0 + 16);
                ahi[mt][3] = *(const uint32_t*)(sm + OFF_AHI + r1 + 16);
                alo[mt][0] = *(const uint32_t*)(sm + OFF_ALO + r0);
                alo[mt][1] = *(const uint32_t*)(sm + OFF_ALO + r1);
                alo[mt][2] = *(const uint32_t*)(sm + OFF_ALO + r0 + 16);
                alo[mt][3] = *(const uint32_t*)(sm + OFF_ALO + r1 + 16);
            }
#pragma unroll
            for (int nt = 0; nt < 8; nt++) {
                int b0 = (warp_n * 64 + nt * 8 + g) * (STRD * 2) + kb;
                uint32_t bhi0 = *(const uint32_t*)(sm + OFF_BHI + b0);
                uint32_t bhi1 = *(const uint32_t*)(sm + OFF_BHI + b0 + 16);
                uint32_t blo0 = *(const uint32_t*)(sm + OFF_BLO + b0);
                uint32_t blo1 = *(const uint32_t*)(sm + OFF_BLO + b0 + 16);
#pragma unroll
                for (int mt = 0; mt < 2; mt++) {
                    mma16816(acc[mt][nt], ahi[mt], bhi0, bhi1);
                    mma16816(acc[mt][nt], ahi[mt], blo0, blo1);
                    mma16816(acc[mt][nt], alo[mt], bhi0, bhi1);
                }
            }
        }
    }

    // ---- epilogue ----
#pragma unroll
    for (int mt = 0; mt < 2; mt++) {
        int row0 = m0 + warp_m * 32 + mt * 16 + g;
#pragma unroll
        for (int nt = 0; nt < 8; nt++) {
            int col = n0 + warp_n * 64 + nt * 8 + t4 * 2;
            float2 lo = make_float2(acc[mt][nt][0], acc[mt][nt][1]);
            float2 hi = make_float2(acc[mt][nt][2], acc[mt][nt][3]);
            if (col < 512) {
                *reinterpret_cast<float2*>(&Q[(size_t)row0 * 512 + col]) = lo;
                *reinterpret_cast<float2*>(&Q[(size_t)(row0 + 8) * 512 + col]) = hi;
            } else {
                int vc = col - 512;
                float2 b2 = *reinterpret_cast<const float2*>(&bias[vc]);
                lo.x += b2.x; lo.y += b2.y;
                hi.x += b2.x; hi.y += b2.y;
                *reinterpret_cast<float2*>(&V[(size_t)row0 * 512 + vc]) = lo;
                *reinterpret_cast<float2*>(&V[(size_t)(row0 + 8) * 512 + vc]) = hi;
            }
        }
    }
}

// ---------------------------------------------------------------------------
// Windowed attention (unchanged, known-good): 32 queries x 128-key band.
// ---------------------------------------------------------------------------
struct P1Tiles { float Qs[QT][33]; float Ks[NKEY][33]; };

__global__ __launch_bounds__(256)
void attn_win(const float* __restrict__ X, const float* __restrict__ Q,
              const float* __restrict__ V, float* __restrict__ O)
{
    __shared__ float Ssm[QT][NKEY];
    __shared__ union SU { P1Tiles p1; float Vs[8][D_MODEL]; } u;

    const int tid = threadIdx.x;
    const int tx = tid & 31;
    const int ty = tid >> 5;
    const int b  = blockIdx.y;
    const int i0 = blockIdx.x * QT;
    const int jstart = i0 - WBACK;

    const float* Xb = X + (size_t)b * S_LEN * D_MODEL;
    const float* Qb = Q + (size_t)b * S_LEN * D_MODEL;
    const float* Vb = V + (size_t)b * S_LEN * D_MODEL;

    float acc[4][4];
#pragma unroll
    for (int i = 0; i < 4; i++)
#pragma unroll
        for (int j = 0; j < 4; j++) acc[i][j] = 0.f;

    for (int k0 = 0; k0 < D_MODEL; k0 += 32) {
        {
            int row = tid >> 3;
            int c4  = (tid & 7) * 4;
            float4 q = *reinterpret_cast<const float4*>(
                &Qb[(size_t)(i0 + row) * D_MODEL + k0 + c4]);
            u.p1.Qs[row][c4 + 0] = q.x; u.p1.Qs[row][c4 + 1] = q.y;
            u.p1.Qs[row][c4 + 2] = q.z; u.p1.Qs[row][c4 + 3] = q.w;
        }
#pragma unroll
        for (int r = 0; r < 4; r++) {
            int idx  = tid + 256 * r;
            int krow = idx >> 3;
            int c4   = (idx & 7) * 4;
            int j    = jstart + krow;
            float4 kv = make_float4(0.f, 0.f, 0.f, 0.f);
            if (j >= 0)
                kv = *reinterpret_cast<const float4*>(
                    &Xb[(size_t)j * D_MODEL + k0 + c4]);
            u.p1.Ks[krow][c4 + 0] = kv.x; u.p1.Ks[krow][c4 + 1] = kv.y;
            u.p1.Ks[krow][c4 + 2] = kv.z; u.p1.Ks[krow][c4 + 3] = kv.w;
        }
        __syncthreads();

#pragma unroll
        for (int kk = 0; kk < 32; kk++) {
            float q[4], kv[4];
#pragma unroll
            for (int ri = 0; ri < 4; ri++) q[ri]  = u.p1.Qs[ty + 8 * ri][kk];
#pragma unroll
            for (int ci = 0; ci < 4; ci++) kv[ci] = u.p1.Ks[tx + 32 * ci][kk];
#pragma unroll
            for (int ri = 0; ri < 4; ri++)
#pragma unroll
                for (int ci = 0; ci < 4; ci++)
                    acc[ri][ci] = fmaf(q[ri], kv[ci], acc[ri][ci]);
        }
        __syncthreads();
    }

    const float scale = 0.04419417382415922f;
#pragma unroll
    for (int ri = 0; ri < 4; ri++) {
        int i = i0 + ty + 8 * ri;
#pragma unroll
        for (int ci = 0; ci < 4; ci++) {
            int c = tx + 32 * ci;
            int j = jstart + c;
            float s;
            if (j < 0 || j > i) s = -1e30f;
            else s = acc[ri][ci] * scale + SLOPE * (float)(j - i);
            Ssm[ty + 8 * ri][c] = s;
        }
    }
    __syncthreads();

    {
        int r = tid >> 3;
        int l = tid & 7;
        float m = -1e30f;
        for (int c = l * 16; c < l * 16 + 16; c++) m = fmaxf(m, Ssm[r][c]);
#pragma unroll
        for (int o = 4; o > 0; o >>= 1)
            m = fmaxf(m, __shfl_xor_sync(0xffffffffu, m, o));
        float sum = 0.f;
        for (int c = l * 16; c < l * 16 + 16; c++) {
            float e = __expf(Ssm[r][c] - m);
            Ssm[r][c] = e;
            sum += e;
        }
#pragma unroll
        for (int o = 4; o > 0; o >>= 1)
            sum += __shfl_xor_sync(0xffffffffu, sum, o);
        float inv = 1.f / sum;
        for (int c = l * 16; c < l * 16 + 16; c++) Ssm[r][c] *= inv;
    }
    __syncthreads();

    float out[4][16];
#pragma unroll
    for (int ri = 0; ri < 4; ri++)
#pragma unroll
        for (int ci = 0; ci < 16; ci++) out[ri][ci] = 0.f;

    for (int kc = 0; kc < NKEY; kc += 8) {
#pragma unroll
        for (int r = 0; r < 4; r++) {
            int idx  = tid + 256 * r;
            int vrow = idx >> 7;
            int c4   = (idx & 127) * 4;
            int j    = jstart + kc + vrow;
            float4 vv = make_float4(0.f, 0.f, 0.f, 0.f);
            if (j >= 0)
                vv = *reinterpret_cast<const float4*>(
                    &Vb[(size_t)j * D_MODEL + c4]);
            *reinterpret_cast<float4*>(&u.Vs[vrow][c4]) = vv;
        }
        __syncthreads();

#pragma unroll
        for (int k = 0; k < 8; k++) {
            float p[4];
#pragma unroll
            for (int ri = 0; ri < 4; ri++) p[ri] = Ssm[ty + 8 * ri][kc + k];
#pragma unroll
            for (int ci = 0; ci < 16; ci++) {
                float v = u.Vs[k][tx + 32 * ci];
#pragma unroll
                for (int ri = 0; ri < 4; ri++)
                    out[ri][ci] = fmaf(p[ri], v, out[ri][ci]);
            }
        }
        __syncthreads();
    }

#pragma unroll
    for (int ri = 0; ri < 4; ri++) {
        int row = i0 + ty + 8 * ri;
#pragma unroll
        for (int ci = 0; ci < 16; ci++)
            O[((size_t)b * S_LEN + row) * D_MODEL + tx + 32 * ci] = out[ri][ci];
    }
}

// ---------------------------------------------------------------------------
extern "C" void kernel_launch(void* const* d_in, const int* in_sizes, int n_in,
                              void* d_out, int out_size)
{
    const float* x   = (const float*)d_in[0];
    const float* Wqk = (const float*)d_in[1];
    const float* Wv  = (const float*)d_in[2];
    const float* bv  = (const float*)d_in[3];
    float* out = (float*)d_out;

    float *Qp = nullptr, *Vp = nullptr;
    cudaGetSymbolAddress((void**)&Qp, g_Q);
    cudaGetSymbolAddress((void**)&Vp, g_V);

    pack_w<<<2048, 256>>>(Wqk, Wv);

    dim3 ggemm(128, 8);                 // 128 M-tiles x 8 N-tiles (N=1024 fused)
    mma_gemm<<<ggemm, 256>>>(x, bv, Qp, Vp);

    dim3 gattn(S_LEN / QT, NB);
    attn_win<<<gattn, 256>>>(x, Qp, Vp, out);
}

// round 6
// speedup vs baseline: 2.1775x; 1.8203x over previous
#include <cuda_runtime.h>
#include <cuda_bf16.h>
#include <cstdint>
#include <math.h>

// Problem constants
#define S_LEN 4096
#define D_MODEL 512
#define SLOPE 0.5f
#define QT 32
#define NKEY 128
#define WBACK 96
#define NB 4

// Scratch
__device__ float g_Q[NB * S_LEN * D_MODEL];
__device__ float g_V[NB * S_LEN * D_MODEL];
// Packed [Wqk | Wv^T], tf32-rounded, layout [n][k] (K-major rows), n=0..1023
__device__ uint32_t g_Wt[1024 * 512];

// ---------------------------------------------------------------------------
// tf32 mma.sync: D += A(16x8 tf32) * B(8x8 tf32), fp32 accum
// ---------------------------------------------------------------------------
__device__ __forceinline__ void mma16808(float* d, const uint32_t* a,
                                         uint32_t b0, uint32_t b1)
{
    asm volatile(
        "mma.sync.aligned.m16n8k8.row.col.f32.tf32.tf32.f32 "
        "{%0,%1,%2,%3}, {%4,%5,%6,%7}, {%8,%9}, {%0,%1,%2,%3};"
        : "+f"(d[0]), "+f"(d[1]), "+f"(d[2]), "+f"(d[3])
        : "r"(a[0]), "r"(a[1]), "r"(a[2]), "r"(a[3]), "r"(b0), "r"(b1));
}

__device__ __forceinline__ uint32_t f2tf32(float x) {
    uint32_t t;
    asm("cvt.rna.tf32.f32 %0, %1;" : "=r"(t) : "f"(x));
    return t;
}

// ---------------------------------------------------------------------------
// Pack [Wqk | Wv^T] -> tf32, layout [n][k]
// ---------------------------------------------------------------------------
__global__ void pack_w(const float* __restrict__ Wqk, const float* __restrict__ Wv)
{
    int idx = blockIdx.x * 256 + threadIdx.x;   // 0..524287
    int n = idx >> 9, k = idx & 511;
    float w = (n < 512) ? Wqk[k * 512 + n] : Wv[(n - 512) * 512 + k];
    g_Wt[idx] = f2tf32(w);
}

// ---------------------------------------------------------------------------
// tf32 mma GEMM: [Q|V][16384, 1024] = x[16384,512] @ W^T, single pass.
// CTA 128x128, 8 warps (4m x 2n), warp tile 32x64, K-chunk 64.
// smem stride 68 words: fragment banks (4r + c) mod 32 -> conflict-free.
// ---------------------------------------------------------------------------
#define STRF 68
#define APLANE (128 * STRF)            // words

__global__ __launch_bounds__(256)
void mma_gemm(const float* __restrict__ X, const float* __restrict__ bias,
              float* __restrict__ Q, float* __restrict__ V)
{
    extern __shared__ uint32_t smw[];
    uint32_t* sA = smw;                // 128 x 68 words
    uint32_t* sB = smw + APLANE;       // 128 x 68 words

    const int tid = threadIdx.x;
    const int wid = tid >> 5;
    const int lane = tid & 31;
    const int g = lane >> 2;          // 0..7
    const int t4 = lane & 3;          // 0..3
    const int warp_m = wid & 3;       // rows 32*warp_m
    const int warp_n = wid >> 2;      // cols 64*warp_n
    const int m0 = blockIdx.x * 128;
    const int n0 = blockIdx.y * 128;

    float acc[2][8][4];
#pragma unroll
    for (int mt = 0; mt < 2; mt++)
#pragma unroll
        for (int nt = 0; nt < 8; nt++)
#pragma unroll
            for (int i = 0; i < 4; i++) acc[mt][nt][i] = 0.f;

    const int lrow = tid >> 4;            // 0..15 (row block per 256-thread pass)
    const int lc4  = (tid & 15) << 2;     // 0,4,..,60

    for (int c = 0; c < 8; c++) {
        const int k0 = c * 64;

        // ---- prefetch globals into regs (overlaps previous chunk's MMAs) ----
        float4 av[8];
        uint4  bv[8];
#pragma unroll
        for (int i = 0; i < 8; i++) {
            int row = lrow + 16 * i;
            av[i] = *reinterpret_cast<const float4*>(
                &X[(size_t)(m0 + row) * 512 + k0 + lc4]);
            bv[i] = *reinterpret_cast<const uint4*>(
                &g_Wt[(size_t)(n0 + row) * 512 + k0 + lc4]);
        }

        if (c) __syncthreads();

#pragma unroll
        for (int i = 0; i < 8; i++) {
            int row = lrow + 16 * i;
            uint4 at;
            at.x = f2tf32(av[i].x); at.y = f2tf32(av[i].y);
            at.z = f2tf32(av[i].z); at.w = f2tf32(av[i].w);
            *reinterpret_cast<uint4*>(&sA[row * STRF + lc4]) = at;
            *reinterpret_cast<uint4*>(&sB[row * STRF + lc4]) = bv[i];
        }
        __syncthreads();

        // ---- compute: 8 k8 steps ----
#pragma unroll
        for (int k8 = 0; k8 < 8; k8++) {
            const int kc = k8 * 8 + t4;
            uint32_t a[2][4];
#pragma unroll
            for (int mt = 0; mt < 2; mt++) {
                int r = warp_m * 32 + mt * 16 + g;
                a[mt][0] = sA[r * STRF + kc];
                a[mt][1] = sA[(r + 8) * STRF + kc];
                a[mt][2] = sA[r * STRF + kc + 4];
                a[mt][3] = sA[(r + 8) * STRF + kc + 4];
            }
#pragma unroll
            for (int nt = 0; nt < 8; nt++) {
                int rn = warp_n * 64 + nt * 8 + g;
                uint32_t b0 = sB[rn * STRF + kc];
                uint32_t b1 = sB[rn * STRF + kc + 4];
#pragma unroll
                for (int mt = 0; mt < 2; mt++)
                    mma16808(acc[mt][nt], a[mt], b0, b1);
            }
        }
    }

    // ---- epilogue ----
#pragma unroll
    for (int mt = 0; mt < 2; mt++) {
        int row0 = m0 + warp_m * 32 + mt * 16 + g;
#pragma unroll
        for (int nt = 0; nt < 8; nt++) {
            int col = n0 + warp_n * 64 + nt * 8 + t4 * 2;
            float2 lo = make_float2(acc[mt][nt][0], acc[mt][nt][1]);
            float2 hi = make_float2(acc[mt][nt][2], acc[mt][nt][3]);
            if (col < 512) {
                *reinterpret_cast<float2*>(&Q[(size_t)row0 * 512 + col]) = lo;
                *reinterpret_cast<float2*>(&Q[(size_t)(row0 + 8) * 512 + col]) = hi;
            } else {
                int vc = col - 512;
                float2 b2 = *reinterpret_cast<const float2*>(&bias[vc]);
                lo.x += b2.x; lo.y += b2.y;
                hi.x += b2.x; hi.y += b2.y;
                *reinterpret_cast<float2*>(&V[(size_t)row0 * 512 + vc]) = lo;
                *reinterpret_cast<float2*>(&V[(size_t)(row0 + 8) * 512 + vc]) = hi;
            }
        }
    }
}

// ---------------------------------------------------------------------------
// Windowed attention (unchanged, known-good): 32 queries x 128-key band.
// ---------------------------------------------------------------------------
struct P1Tiles { float Qs[QT][33]; float Ks[NKEY][33]; };

__global__ __launch_bounds__(256)
void attn_win(const float* __restrict__ X, const float* __restrict__ Q,
              const float* __restrict__ V, float* __restrict__ O)
{
    __shared__ float Ssm[QT][NKEY];
    __shared__ union SU { P1Tiles p1; float Vs[8][D_MODEL]; } u;

    const int tid = threadIdx.x;
    const int tx = tid & 31;
    const int ty = tid >> 5;
    const int b  = blockIdx.y;
    const int i0 = blockIdx.x * QT;
    const int jstart = i0 - WBACK;

    const float* Xb = X + (size_t)b * S_LEN * D_MODEL;
    const float* Qb = Q + (size_t)b * S_LEN * D_MODEL;
    const float* Vb = V + (size_t)b * S_LEN * D_MODEL;

    float acc[4][4];
#pragma unroll
    for (int i = 0; i < 4; i++)
#pragma unroll
        for (int j = 0; j < 4; j++) acc[i][j] = 0.f;

    for (int k0 = 0; k0 < D_MODEL; k0 += 32) {
        {
            int row = tid >> 3;
            int c4  = (tid & 7) * 4;
            float4 q = *reinterpret_cast<const float4*>(
                &Qb[(size_t)(i0 + row) * D_MODEL + k0 + c4]);
            u.p1.Qs[row][c4 + 0] = q.x; u.p1.Qs[row][c4 + 1] = q.y;
            u.p1.Qs[row][c4 + 2] = q.z; u.p1.Qs[row][c4 + 3] = q.w;
        }
#pragma unroll
        for (int r = 0; r < 4; r++) {
            int idx  = tid + 256 * r;
            int krow = idx >> 3;
            int c4   = (idx & 7) * 4;
            int j    = jstart + krow;
            float4 kv = make_float4(0.f, 0.f, 0.f, 0.f);
            if (j >= 0)
                kv = *reinterpret_cast<const float4*>(
                    &Xb[(size_t)j * D_MODEL + k0 + c4]);
            u.p1.Ks[krow][c4 + 0] = kv.x; u.p1.Ks[krow][c4 + 1] = kv.y;
            u.p1.Ks[krow][c4 + 2] = kv.z; u.p1.Ks[krow][c4 + 3] = kv.w;
        }
        __syncthreads();

#pragma unroll
        for (int kk = 0; kk < 32; kk++) {
            float q[4], kv[4];
#pragma unroll
            for (int ri = 0; ri < 4; ri++) q[ri]  = u.p1.Qs[ty + 8 * ri][kk];
#pragma unroll
            for (int ci = 0; ci < 4; ci++) kv[ci] = u.p1.Ks[tx + 32 * ci][kk];
#pragma unroll
            for (int ri = 0; ri < 4; ri++)
#pragma unroll
                for (int ci = 0; ci < 4; ci++)
                    acc[ri][ci] = fmaf(q[ri], kv[ci], acc[ri][ci]);
        }
        __syncthreads();
    }

    const float scale = 0.04419417382415922f;
#pragma unroll
    for (int ri = 0; ri < 4; ri++) {
        int i = i0 + ty + 8 * ri;
#pragma unroll
        for (int ci = 0; ci < 4; ci++) {
            int c = tx + 32 * ci;
            int j = jstart + c;
            float s;
            if (j < 0 || j > i) s = -1e30f;
            else s = acc[ri][ci] * scale + SLOPE * (float)(j - i);
            Ssm[ty + 8 * ri][c] = s;
        }
    }
    __syncthreads();

    {
        int r = tid >> 3;
        int l = tid & 7;
        float m = -1e30f;
        for (int c = l * 16; c < l * 16 + 16; c++) m = fmaxf(m, Ssm[r][c]);
#pragma unroll
        for (int o = 4; o > 0; o >>= 1)
            m = fmaxf(m, __shfl_xor_sync(0xffffffffu, m, o));
        float sum = 0.f;
        for (int c = l * 16; c < l * 16 + 16; c++) {
            float e = __expf(Ssm[r][c] - m);
            Ssm[r][c] = e;
            sum += e;
        }
#pragma unroll
        for (int o = 4; o > 0; o >>= 1)
            sum += __shfl_xor_sync(0xffffffffu, sum, o);
        float inv = 1.f / sum;
        for (int c = l * 16; c < l * 16 + 16; c++) Ssm[r][c] *= inv;
    }
    __syncthreads();

    float out[4][16];
#pragma unroll
    for (int ri = 0; ri < 4; ri++)
#pragma unroll
        for (int ci = 0; ci < 16; ci++) out[ri][ci] = 0.f;

    for (int kc = 0; kc < NKEY; kc += 8) {
#pragma unroll
        for (int r = 0; r < 4; r++) {
            int idx  = tid + 256 * r;
            int vrow = idx >> 7;
            int c4   = (idx & 127) * 4;
            int j    = jstart + kc + vrow;
            float4 vv = make_float4(0.f, 0.f, 0.f, 0.f);
            if (j >= 0)
                vv = *reinterpret_cast<const float4*>(
                    &Vb[(size_t)j * D_MODEL + c4]);
            *reinterpret_cast<float4*>(&u.Vs[vrow][c4]) = vv;
        }
        __syncthreads();

#pragma unroll
        for (int k = 0; k < 8; k++) {
            float p[4];
#pragma unroll
            for (int ri = 0; ri < 4; ri++) p[ri] = Ssm[ty + 8 * ri][kc + k];
#pragma unroll
            for (int ci = 0; ci < 16; ci++) {
                float v = u.Vs[k][tx + 32 * ci];
#pragma unroll
                for (int ri = 0; ri < 4; ri++)
                    out[ri][ci] = fmaf(p[ri], v, out[ri][ci]);
            }
        }
        __syncthreads();
    }

#pragma unroll
    for (int ri = 0; ri < 4; ri++) {
        int row = i0 + ty + 8 * ri;
#pragma unroll
        for (int ci = 0; ci < 16; ci++)
            O[((size_t)b * S_LEN + row) * D_MODEL + tx + 32 * ci] = out[ri][ci];
    }
}

// ---------------------------------------------------------------------------
extern "C" void kernel_launch(void* const* d_in, const int* in_sizes, int n_in,
                              void* d_out, int out_size)
{
    const float* x   = (const float*)d_in[0];
    const float* Wqk = (const float*)d_in[1];
    const float* Wv  = (const float*)d_in[2];
    const float* bv  = (const float*)d_in[3];
    float* out = (float*)d_out;

    float *Qp = nullptr, *Vp = nullptr;
    cudaGetSymbolAddress((void**)&Qp, g_Q);
    cudaGetSymbolAddress((void**)&Vp, g_V);

    const int gemm_smem = 2 * APLANE * 4;   // 69632 B
    cudaFuncSetAttribute(mma_gemm, cudaFuncAttributeMaxDynamicSharedMemorySize,
                         gemm_smem);

    pack_w<<<2048, 256>>>(Wqk, Wv);

    dim3 ggemm(128, 8);                 // 128 M-tiles x 8 N-tiles (N=1024 fused)
    mma_gemm<<<ggemm, 256, gemm_smem>>>(x, bv, Qp, Vp);

    dim3 gattn(S_LEN / QT, NB);
    attn_win<<<gattn, 256>>>(x, Qp, Vp, out);
}

// round 7
// speedup vs baseline: 3.2464x; 1.4909x over previous
#include <cuda_runtime.h>
#include <cuda_bf16.h>
#include <cstdint>
#include <math.h>

// Problem constants
#define S_LEN 4096
#define D_MODEL 512
#define SLOPE 0.5f
#define QT 32
#define NKEY 128
#define WBACK 96
#define NB 4

// Scratch
__device__ float g_Q[NB * S_LEN * D_MODEL];
__device__ float g_V[NB * S_LEN * D_MODEL];
// Packed [Wqk | Wv^T], tf32-rounded, layout [n][k] (K-major rows), n=0..1023
__device__ uint32_t g_Wt[1024 * 512];

// ---------------------------------------------------------------------------
// tf32 mma.sync: D += A(16x8 tf32) * B(8x8 tf32), fp32 accum
// ---------------------------------------------------------------------------
__device__ __forceinline__ void mma16808(float* d, const uint32_t* a,
                                         uint32_t b0, uint32_t b1)
{
    asm volatile(
        "mma.sync.aligned.m16n8k8.row.col.f32.tf32.tf32.f32 "
        "{%0,%1,%2,%3}, {%4,%5,%6,%7}, {%8,%9}, {%0,%1,%2,%3};"
        : "+f"(d[0]), "+f"(d[1]), "+f"(d[2]), "+f"(d[3])
        : "r"(a[0]), "r"(a[1]), "r"(a[2]), "r"(a[3]), "r"(b0), "r"(b1));
}

__device__ __forceinline__ uint32_t f2tf32(float x) {
    uint32_t t;
    asm("cvt.rna.tf32.f32 %0, %1;" : "=r"(t) : "f"(x));
    return t;
}

// ---------------------------------------------------------------------------
// Pack [Wqk | Wv^T] -> tf32, layout [n][k]
// ---------------------------------------------------------------------------
__global__ void pack_w(const float* __restrict__ Wqk, const float* __restrict__ Wv)
{
    int idx = blockIdx.x * 256 + threadIdx.x;   // 0..524287
    int n = idx >> 9, k = idx & 511;
    float w = (n < 512) ? Wqk[k * 512 + n] : Wv[(n - 512) * 512 + k];
    g_Wt[idx] = f2tf32(w);
}

// ---------------------------------------------------------------------------
// tf32 mma GEMM: [Q|V][16384, 1024] = x[16384,512] @ W^T  (unchanged, R5)
// ---------------------------------------------------------------------------
#define STRF 68
#define APLANE (128 * STRF)

__global__ __launch_bounds__(256)
void mma_gemm(const float* __restrict__ X, const float* __restrict__ bias,
              float* __restrict__ Q, float* __restrict__ V)
{
    extern __shared__ uint32_t smw[];
    uint32_t* sA = smw;
    uint32_t* sB = smw + APLANE;

    const int tid = threadIdx.x;
    const int wid = tid >> 5;
    const int lane = tid & 31;
    const int g = lane >> 2;
    const int t4 = lane & 3;
    const int warp_m = wid & 3;
    const int warp_n = wid >> 2;
    const int m0 = blockIdx.x * 128;
    const int n0 = blockIdx.y * 128;

    float acc[2][8][4];
#pragma unroll
    for (int mt = 0; mt < 2; mt++)
#pragma unroll
        for (int nt = 0; nt < 8; nt++)
#pragma unroll
            for (int i = 0; i < 4; i++) acc[mt][nt][i] = 0.f;

    const int lrow = tid >> 4;
    const int lc4  = (tid & 15) << 2;

    for (int c = 0; c < 8; c++) {
        const int k0 = c * 64;
        float4 av[8];
        uint4  bv[8];
#pragma unroll
        for (int i = 0; i < 8; i++) {
            int row = lrow + 16 * i;
            av[i] = *reinterpret_cast<const float4*>(
                &X[(size_t)(m0 + row) * 512 + k0 + lc4]);
            bv[i] = *reinterpret_cast<const uint4*>(
                &g_Wt[(size_t)(n0 + row) * 512 + k0 + lc4]);
        }
        if (c) __syncthreads();
#pragma unroll
        for (int i = 0; i < 8; i++) {
            int row = lrow + 16 * i;
            uint4 at;
            at.x = f2tf32(av[i].x); at.y = f2tf32(av[i].y);
            at.z = f2tf32(av[i].z); at.w = f2tf32(av[i].w);
            *reinterpret_cast<uint4*>(&sA[row * STRF + lc4]) = at;
            *reinterpret_cast<uint4*>(&sB[row * STRF + lc4]) = bv[i];
        }
        __syncthreads();
#pragma unroll
        for (int k8 = 0; k8 < 8; k8++) {
            const int kc = k8 * 8 + t4;
            uint32_t a[2][4];
#pragma unroll
            for (int mt = 0; mt < 2; mt++) {
                int r = warp_m * 32 + mt * 16 + g;
                a[mt][0] = sA[r * STRF + kc];
                a[mt][1] = sA[(r + 8) * STRF + kc];
                a[mt][2] = sA[r * STRF + kc + 4];
                a[mt][3] = sA[(r + 8) * STRF + kc + 4];
            }
#pragma unroll
            for (int nt = 0; nt < 8; nt++) {
                int rn = warp_n * 64 + nt * 8 + g;
                uint32_t b0 = sB[rn * STRF + kc];
                uint32_t b1 = sB[rn * STRF + kc + 4];
#pragma unroll
                for (int mt = 0; mt < 2; mt++)
                    mma16808(acc[mt][nt], a[mt], b0, b1);
            }
        }
    }

#pragma unroll
    for (int mt = 0; mt < 2; mt++) {
        int row0 = m0 + warp_m * 32 + mt * 16 + g;
#pragma unroll
        for (int nt = 0; nt < 8; nt++) {
            int col = n0 + warp_n * 64 + nt * 8 + t4 * 2;
            float2 lo = make_float2(acc[mt][nt][0], acc[mt][nt][1]);
            float2 hi = make_float2(acc[mt][nt][2], acc[mt][nt][3]);
            if (col < 512) {
                *reinterpret_cast<float2*>(&Q[(size_t)row0 * 512 + col]) = lo;
                *reinterpret_cast<float2*>(&Q[(size_t)(row0 + 8) * 512 + col]) = hi;
            } else {
                int vc = col - 512;
                float2 b2 = *reinterpret_cast<const float2*>(&bias[vc]);
                lo.x += b2.x; lo.y += b2.y;
                hi.x += b2.x; hi.y += b2.y;
                *reinterpret_cast<float2*>(&V[(size_t)row0 * 512 + vc]) = lo;
                *reinterpret_cast<float2*>(&V[(size_t)(row0 + 8) * 512 + vc]) = hi;
            }
        }
    }
}

// ---------------------------------------------------------------------------
// Tensor-core windowed attention. CTA = 32 queries x 128-key band, 8 warps.
// Phase1: S = Q @ K^T (tf32 mma, k-chunks of 64) + scale/ALiBi/mask -> smem
// Phase2: softmax (8 lanes/row), store P tf32-rounded in place
// Phase3: O = P @ V (tf32 mma, 64-channel chunks, direct gmem write)
// Smem strides: SsmP 132, Qs/Ks 68, Vc 72 -> all fragment loads conflict-free.
// ---------------------------------------------------------------------------
#define SP_STR 132
#define QK_STR 68
#define VC_STR 72
#define OFF_SP 0
#define OFF_QS (32 * SP_STR)                 // words
#define OFF_KS (OFF_QS + 32 * QK_STR)
#define OFF_VC OFF_QS
#define ATTN_SMEM_W (OFF_KS + 128 * QK_STR)  // 15104 words = 60416 B

__global__ __launch_bounds__(256)
void attn_tc(const float* __restrict__ X, const float* __restrict__ Q,
             const float* __restrict__ V, float* __restrict__ O)
{
    extern __shared__ uint32_t smw[];
    float* sP = reinterpret_cast<float*>(smw + OFF_SP);
    uint32_t* sQ = smw + OFF_QS;
    uint32_t* sK = smw + OFF_KS;
    uint32_t* sV = smw + OFF_VC;

    const int tid = threadIdx.x;
    const int wid = tid >> 5;
    const int lane = tid & 31;
    const int g = lane >> 2;
    const int t4 = lane & 3;
    const int b  = blockIdx.y;
    const int i0 = blockIdx.x * QT;
    const int jstart = i0 - WBACK;

    const float* Xb = X + (size_t)b * S_LEN * D_MODEL;
    const float* Qb = Q + (size_t)b * S_LEN * D_MODEL;
    const float* Vb = V + (size_t)b * S_LEN * D_MODEL;

    // ================= Phase 1: scores =================
    const int wm = wid & 1;        // m-tile (16 rows)
    const int wn = wid >> 1;       // 0..3 -> 32 cols each
    float accs[4][4];
#pragma unroll
    for (int nt = 0; nt < 4; nt++)
#pragma unroll
        for (int i = 0; i < 4; i++) accs[nt][i] = 0.f;

    for (int c = 0; c < 8; c++) {
        const int k0 = c * 64;
        // Q chunk 32x64: 8 floats/thread
        {
            int row = tid >> 3, c8 = (tid & 7) * 8;
            const float* src = &Qb[(size_t)(i0 + row) * 512 + k0 + c8];
            float4 q0 = *reinterpret_cast<const float4*>(src);
            float4 q1 = *reinterpret_cast<const float4*>(src + 4);
            if (c) __syncthreads();
            uint32_t* d = &sQ[row * QK_STR + c8];
            d[0] = f2tf32(q0.x); d[1] = f2tf32(q0.y);
            d[2] = f2tf32(q0.z); d[3] = f2tf32(q0.w);
            d[4] = f2tf32(q1.x); d[5] = f2tf32(q1.y);
            d[6] = f2tf32(q1.z); d[7] = f2tf32(q1.w);
        }
        // K chunk 128x64: 32 floats/thread
#pragma unroll
        for (int i = 0; i < 8; i++) {
            int idx = tid + 256 * i;
            int row = idx >> 4, c4 = (idx & 15) * 4;
            int j = jstart + row;
            float4 kv = make_float4(0.f, 0.f, 0.f, 0.f);
            if (j >= 0)
                kv = *reinterpret_cast<const float4*>(
                    &Xb[(size_t)j * 512 + k0 + c4]);
            uint32_t* d = &sK[row * QK_STR + c4];
            d[0] = f2tf32(kv.x); d[1] = f2tf32(kv.y);
            d[2] = f2tf32(kv.z); d[3] = f2tf32(kv.w);
        }
        __syncthreads();

#pragma unroll
        for (int k8 = 0; k8 < 8; k8++) {
            const int kc = k8 * 8 + t4;
            uint32_t a[4];
            int r = wm * 16 + g;
            a[0] = sQ[r * QK_STR + kc];
            a[1] = sQ[(r + 8) * QK_STR + kc];
            a[2] = sQ[r * QK_STR + kc + 4];
            a[3] = sQ[(r + 8) * QK_STR + kc + 4];
#pragma unroll
            for (int nt = 0; nt < 4; nt++) {
                int rn = wn * 32 + nt * 8 + g;
                uint32_t b0 = sK[rn * QK_STR + kc];
                uint32_t b1 = sK[rn * QK_STR + kc + 4];
                mma16808(accs[nt], a, b0, b1);
            }
        }
        __syncthreads();
    }

    // scale + ALiBi + causal mask -> sP
    const float scale = 0.04419417382415922f;
#pragma unroll
    for (int nt = 0; nt < 4; nt++) {
#pragma unroll
        for (int h = 0; h < 2; h++) {       // row half: g vs g+8
            int row = wm * 16 + g + 8 * h;
            int i = i0 + row;
#pragma unroll
            for (int cpair = 0; cpair < 2; cpair++) {
                int col = wn * 32 + nt * 8 + t4 * 2 + cpair;
                int j = jstart + col;
                float v = accs[nt][h * 2 + cpair];
                float s = (j < 0 || j > i) ? -1e30f
                        : v * scale + SLOPE * (float)(j - i);
                sP[row * SP_STR + col] = s;
            }
        }
    }
    __syncthreads();

    // ================= Phase 2: softmax =================
    {
        int r = tid >> 3;
        int l = tid & 7;
        float* row = &sP[r * SP_STR];
        float m = -1e30f;
        for (int c = l * 16; c < l * 16 + 16; c++) m = fmaxf(m, row[c]);
#pragma unroll
        for (int o = 4; o > 0; o >>= 1)
            m = fmaxf(m, __shfl_xor_sync(0xffffffffu, m, o));
        float sum = 0.f;
        float e[16];
#pragma unroll
        for (int k = 0; k < 16; k++) {
            e[k] = __expf(row[l * 16 + k] - m);
            sum += e[k];
        }
#pragma unroll
        for (int o = 4; o > 0; o >>= 1)
            sum += __shfl_xor_sync(0xffffffffu, sum, o);
        float inv = 1.f / sum;
#pragma unroll
        for (int k = 0; k < 16; k++)
            row[l * 16 + k] = __uint_as_float(f2tf32(e[k] * inv));
    }
    __syncthreads();

    // ================= Phase 3: O = P @ V =================
    const int wn8 = wid >> 1;      // 0..3 -> 16 cols within 64-chunk
    const uint32_t* sPu = reinterpret_cast<const uint32_t*>(sP);

    for (int ch = 0; ch < 8; ch++) {
        const int e0 = ch * 64;
        // V chunk 128x64 -> sV (zero-fill j<0)
#pragma unroll
        for (int i = 0; i < 8; i++) {
            int idx = tid + 256 * i;
            int row = idx >> 4, c4 = (idx & 15) * 4;
            int j = jstart + row;
            float4 vv = make_float4(0.f, 0.f, 0.f, 0.f);
            if (j >= 0)
                vv = *reinterpret_cast<const float4*>(
                    &Vb[(size_t)j * 512 + e0 + c4]);
            uint32_t* d = &sV[row * VC_STR + c4];
            d[0] = f2tf32(vv.x); d[1] = f2tf32(vv.y);
            d[2] = f2tf32(vv.z); d[3] = f2tf32(vv.w);
        }
        __syncthreads();

        float acco[2][4];
#pragma unroll
        for (int nt = 0; nt < 2; nt++)
#pragma unroll
            for (int i = 0; i < 4; i++) acco[nt][i] = 0.f;

#pragma unroll
        for (int k8 = 0; k8 < 16; k8++) {
            const int kc = k8 * 8 + t4;
            uint32_t a[4];
            int r = wm * 16 + g;
            a[0] = sPu[r * SP_STR + kc];
            a[1] = sPu[(r + 8) * SP_STR + kc];
            a[2] = sPu[r * SP_STR + kc + 4];
            a[3] = sPu[(r + 8) * SP_STR + kc + 4];
#pragma unroll
            for (int nt = 0; nt < 2; nt++) {
                int nf = wn8 * 16 + nt * 8 + g;
                uint32_t b0 = sV[(k8 * 8 + t4) * VC_STR + nf];
                uint32_t b1 = sV[(k8 * 8 + t4 + 4) * VC_STR + nf];
                mma16808(acco[nt], a, b0, b1);
            }
        }

        // write out
#pragma unroll
        for (int nt = 0; nt < 2; nt++) {
            int col = e0 + wn8 * 16 + nt * 8 + t4 * 2;
            int row0 = i0 + wm * 16 + g;
            *reinterpret_cast<float2*>(
                &O[((size_t)b * S_LEN + row0) * 512 + col]) =
                make_float2(acco[nt][0], acco[nt][1]);
            *reinterpret_cast<float2*>(
                &O[((size_t)b * S_LEN + row0 + 8) * 512 + col]) =
                make_float2(acco[nt][2], acco[nt][3]);
        }
        __syncthreads();
    }
}

// ---------------------------------------------------------------------------
extern "C" void kernel_launch(void* const* d_in, const int* in_sizes, int n_in,
                              void* d_out, int out_size)
{
    const float* x   = (const float*)d_in[0];
    const float* Wqk = (const float*)d_in[1];
    const float* Wv  = (const float*)d_in[2];
    const float* bv  = (const float*)d_in[3];
    float* out = (float*)d_out;

    float *Qp = nullptr, *Vp = nullptr;
    cudaGetSymbolAddress((void**)&Qp, g_Q);
    cudaGetSymbolAddress((void**)&Vp, g_V);

    const int gemm_smem = 2 * APLANE * 4;
    cudaFuncSetAttribute(mma_gemm, cudaFuncAttributeMaxDynamicSharedMemorySize,
                         gemm_smem);
    const int attn_smem = ATTN_SMEM_W * 4;
    cudaFuncSetAttribute(attn_tc, cudaFuncAttributeMaxDynamicSharedMemorySize,
                         attn_smem);

    pack_w<<<2048, 256>>>(Wqk, Wv);

    dim3 ggemm(128, 8);
    mma_gemm<<<ggemm, 256, gemm_smem>>>(x, bv, Qp, Vp);

    dim3 gattn(S_LEN / QT, NB);
    attn_tc<<<gattn, 256, attn_smem>>>(x, Qp, Vp, out);
}